// round 1
// baseline (speedup 1.0000x reference)
#include <cuda_runtime.h>
#include <cuda_bf16.h>

#define IMG_H 256
#define IMG_W 256
#define NB 4
#define NK 4

// Accumulators: [b][0..3] = numerator_k, [b][4..7] = denominator_k
__device__ float g_acc[NB][8];

__global__ void sncl_init_kernel() {
    int t = threadIdx.x;
    if (t < NB * 8) ((float*)g_acc)[t] = 0.0f;
}

// 21 active taps: dx^2+dy^2 <= 5, spatial weight exp(-dsq/16)
__global__ __launch_bounds__(256, 4)
void sncl_main_kernel(const float* __restrict__ image, const float* __restrict__ enc) {
    const int b   = blockIdx.z;
    const int tx0 = blockIdx.x * 32;
    const int ty0 = blockIdx.y * 8;

    __shared__ float  sgray[12][36];
    __shared__ float4 senc [12][36];
    __shared__ float  part [8][8];

    const int tid = threadIdx.y * 32 + threadIdx.x;
    const float* img0 = image + (size_t)b * 3 * IMG_H * IMG_W;
    const float* e0   = enc   + (size_t)b * 4 * IMG_H * IMG_W;
    const int HW = IMG_H * IMG_W;

    // Cooperative halo load: 36x12 = 432 cells, gray = mean of 3 channels,
    // enc packed into float4. Out-of-bounds => 0 (zero padding semantics).
    for (int i = tid; i < 12 * 36; i += 256) {
        int ly = i / 36, lx = i - ly * 36;
        int gy = ty0 - 2 + ly, gx = tx0 - 2 + lx;
        float g = 0.0f;
        float4 e = make_float4(0.f, 0.f, 0.f, 0.f);
        if ((unsigned)gy < IMG_H && (unsigned)gx < IMG_W) {
            int off = gy * IMG_W + gx;
            g = (img0[off] + img0[HW + off] + img0[2 * HW + off]) * (1.0f / 3.0f);
            e.x = e0[off];
            e.y = e0[HW + off];
            e.z = e0[2 * HW + off];
            e.w = e0[3 * HW + off];
        }
        sgray[ly][lx] = g;
        senc [ly][lx] = e;
    }
    __syncthreads();

    const int lx = threadIdx.x + 2;
    const int ly = threadIdx.y + 2;
    const float  c  = sgray[ly][lx];
    const float4 ec = senc [ly][lx];

    // Tap table: dy, dx, dw = exp(-(dy^2+dx^2)/16)
    const int   DYv[21] = {-2,-2,-2, -1,-1,-1,-1,-1, 0,0,0,0,0, 1,1,1,1,1, 2,2,2};
    const int   DXv[21] = {-1, 0, 1, -2,-1, 0, 1, 2, -2,-1,0,1,2, -2,-1,0,1,2, -1,0,1};
    const float DWv[21] = {
        0.73161563f, 0.77880078f, 0.73161563f,
        0.73161563f, 0.88249690f, 0.93941306f, 0.88249690f, 0.73161563f,
        0.77880078f, 0.93941306f, 1.00000000f, 0.93941306f, 0.77880078f,
        0.73161563f, 0.88249690f, 0.93941306f, 0.88249690f, 0.73161563f,
        0.73161563f, 0.77880078f, 0.73161563f
    };

    float wsum = 0.0f;
    float4 nom = make_float4(0.f, 0.f, 0.f, 0.f);
    #pragma unroll
    for (int p = 0; p < 21; p++) {
        float g = sgray[ly + DYv[p]][lx + DXv[p]];
        float d = g - c;
        float w = DWv[p] * __expf(d * d * (-1.0f / 100.0f));
        wsum += w;
        float4 e = senc[ly + DYv[p]][lx + DXv[p]];
        nom.x += w * e.x;
        nom.y += w * e.y;
        nom.z += w * e.z;
        nom.w += w * e.w;
    }

    float vals[8];
    vals[0] = ec.x * nom.x;  vals[1] = ec.y * nom.y;
    vals[2] = ec.z * nom.z;  vals[3] = ec.w * nom.w;
    vals[4] = ec.x * wsum;   vals[5] = ec.y * wsum;
    vals[6] = ec.z * wsum;   vals[7] = ec.w * wsum;

    // Warp reduce (blockDim.x == 32, so warp == threadIdx.y)
    #pragma unroll
    for (int o = 16; o > 0; o >>= 1) {
        #pragma unroll
        for (int j = 0; j < 8; j++)
            vals[j] += __shfl_down_sync(0xffffffffu, vals[j], o);
    }
    if (threadIdx.x == 0) {
        #pragma unroll
        for (int j = 0; j < 8; j++)
            part[threadIdx.y][j] = vals[j];
    }
    __syncthreads();

    if (tid < 8) {
        float s = 0.0f;
        #pragma unroll
        for (int w = 0; w < 8; w++) s += part[w][tid];
        atomicAdd(&g_acc[b][tid], s);
    }
}

__global__ void sncl_final_kernel(float* __restrict__ out) {
    if (threadIdx.x == 0) {
        float total = 0.0f;
        #pragma unroll
        for (int b = 0; b < NB; b++) {
            float s = 0.0f;
            #pragma unroll
            for (int k = 0; k < NK; k++)
                s += g_acc[b][k] / (g_acc[b][4 + k] + 1e-8f);
            total += (float)NK - s;
        }
        out[0] = total * (1.0f / NB);
    }
}

extern "C" void kernel_launch(void* const* d_in, const int* in_sizes, int n_in,
                              void* d_out, int out_size) {
    const float* image = (const float*)d_in[0];
    const float* enc   = (const float*)d_in[1];
    float* out = (float*)d_out;

    sncl_init_kernel<<<1, 32>>>();
    dim3 blk(32, 8, 1);
    dim3 grd(IMG_W / 32, IMG_H / 8, NB);
    sncl_main_kernel<<<grd, blk>>>(image, enc);
    sncl_final_kernel<<<1, 32>>>(out);
}

// round 2
// speedup vs baseline: 1.0173x; 1.0173x over previous
#include <cuda_runtime.h>
#include <cuda_bf16.h>

#define IMG_H 256
#define IMG_W 256
#define NB 4
#define NK 4
#define GRID_BLOCKS (8 * 32 * NB)   // (256/32) x (256/8) x 4 = 1024

// Accumulators: [b][0..3] = numerator_k, [b][4..7] = denominator_k
// Zero-initialized at module load; last block resets them after each run,
// so every graph replay starts from zero (deterministic).
__device__ float        g_acc[NB][8];
__device__ unsigned int g_ticket;

// 21 active taps: dx^2+dy^2 <= 5, spatial weight exp(-dsq/16)
__global__ __launch_bounds__(256, 4)
void sncl_fused_kernel(const float* __restrict__ image,
                       const float* __restrict__ enc,
                       float* __restrict__ out) {
    const int b   = blockIdx.z;
    const int tx0 = blockIdx.x * 32;
    const int ty0 = blockIdx.y * 8;

    __shared__ float  sgray[12][36];
    __shared__ float4 senc [12][36];
    __shared__ float  part [8][8];

    const int tid = threadIdx.y * 32 + threadIdx.x;
    const float* img0 = image + (size_t)b * 3 * IMG_H * IMG_W;
    const float* e0   = enc   + (size_t)b * 4 * IMG_H * IMG_W;
    const int HW = IMG_H * IMG_W;

    // Cooperative halo load: 36x12 = 432 cells. gray = mean of 3 channels,
    // enc packed into float4. Out-of-bounds => 0 (zero-padding semantics).
    for (int i = tid; i < 12 * 36; i += 256) {
        int ly = i / 36, lx = i - ly * 36;
        int gy = ty0 - 2 + ly, gx = tx0 - 2 + lx;
        float g = 0.0f;
        float4 e = make_float4(0.f, 0.f, 0.f, 0.f);
        if ((unsigned)gy < IMG_H && (unsigned)gx < IMG_W) {
            int off = gy * IMG_W + gx;
            g = (img0[off] + img0[HW + off] + img0[2 * HW + off]) * (1.0f / 3.0f);
            e.x = e0[off];
            e.y = e0[HW + off];
            e.z = e0[2 * HW + off];
            e.w = e0[3 * HW + off];
        }
        sgray[ly][lx] = g;
        senc [ly][lx] = e;
    }
    __syncthreads();

    const int lx = threadIdx.x + 2;
    const int ly = threadIdx.y + 2;
    const float  c  = sgray[ly][lx];
    const float4 ec = senc [ly][lx];

    const int   DYv[21] = {-2,-2,-2, -1,-1,-1,-1,-1, 0,0,0,0,0, 1,1,1,1,1, 2,2,2};
    const int   DXv[21] = {-1, 0, 1, -2,-1, 0, 1, 2, -2,-1,0,1,2, -2,-1,0,1,2, -1,0,1};
    const float DWv[21] = {
        0.73161563f, 0.77880078f, 0.73161563f,
        0.73161563f, 0.88249690f, 0.93941306f, 0.88249690f, 0.73161563f,
        0.77880078f, 0.93941306f, 1.00000000f, 0.93941306f, 0.77880078f,
        0.73161563f, 0.88249690f, 0.93941306f, 0.88249690f, 0.73161563f,
        0.73161563f, 0.77880078f, 0.73161563f
    };

    float wsum = 0.0f;
    float4 nom = make_float4(0.f, 0.f, 0.f, 0.f);
    #pragma unroll
    for (int p = 0; p < 21; p++) {
        float g = sgray[ly + DYv[p]][lx + DXv[p]];
        float d = g - c;
        // x = d^2/100 in [0, 0.01]; exp(-x) ~= 1 - x + x^2/2 - x^3/6
        // truncation error <= x^4/24 ~= 4e-10 -- far below 1e-3 tolerance.
        float x = d * d * 0.01f;
        float p3 = fmaf(x, -(1.0f / 6.0f), 0.5f);
        float p2 = fmaf(x, p3, -1.0f);
        float ew = fmaf(x, p2, 1.0f);
        float w = DWv[p] * ew;
        wsum += w;
        float4 e = senc[ly + DYv[p]][lx + DXv[p]];
        nom.x += w * e.x;
        nom.y += w * e.y;
        nom.z += w * e.z;
        nom.w += w * e.w;
    }

    float vals[8];
    vals[0] = ec.x * nom.x;  vals[1] = ec.y * nom.y;
    vals[2] = ec.z * nom.z;  vals[3] = ec.w * nom.w;
    vals[4] = ec.x * wsum;   vals[5] = ec.y * wsum;
    vals[6] = ec.z * wsum;   vals[7] = ec.w * wsum;

    // Warp reduce (blockDim.x == 32, warp == threadIdx.y)
    #pragma unroll
    for (int o = 16; o > 0; o >>= 1) {
        #pragma unroll
        for (int j = 0; j < 8; j++)
            vals[j] += __shfl_down_sync(0xffffffffu, vals[j], o);
    }
    if (threadIdx.x == 0) {
        #pragma unroll
        for (int j = 0; j < 8; j++)
            part[threadIdx.y][j] = vals[j];
    }
    __syncthreads();

    if (tid < 8) {
        float s = 0.0f;
        #pragma unroll
        for (int w = 0; w < 8; w++) s += part[w][tid];
        atomicAdd(&g_acc[b][tid], s);
    }
    __syncthreads();

    // Last-block finalize (threadfence reduction pattern)
    __shared__ bool is_last;
    if (tid == 0) {
        __threadfence();
        unsigned int old = atomicAdd(&g_ticket, 1u);
        is_last = (old == (unsigned int)(GRID_BLOCKS - 1));
    }
    __syncthreads();

    if (is_last && tid == 0) {
        __threadfence();  // make all blocks' atomicAdds visible
        float total = 0.0f;
        #pragma unroll
        for (int bb = 0; bb < NB; bb++) {
            float s = 0.0f;
            #pragma unroll
            for (int k = 0; k < NK; k++)
                s += g_acc[bb][k] / (g_acc[bb][4 + k] + 1e-8f);
            total += (float)NK - s;
        }
        out[0] = total * (1.0f / NB);
        // Self-clean for the next graph replay
        #pragma unroll
        for (int j = 0; j < NB * 8; j++) ((float*)g_acc)[j] = 0.0f;
        __threadfence();
        g_ticket = 0u;
    }
}

extern "C" void kernel_launch(void* const* d_in, const int* in_sizes, int n_in,
                              void* d_out, int out_size) {
    const float* image = (const float*)d_in[0];
    const float* enc   = (const float*)d_in[1];
    float* out = (float*)d_out;

    dim3 blk(32, 8, 1);
    dim3 grd(IMG_W / 32, IMG_H / 8, NB);
    sncl_fused_kernel<<<grd, blk>>>(image, enc, out);
}

// round 3
// speedup vs baseline: 1.1572x; 1.1376x over previous
#include <cuda_runtime.h>
#include <cuda_bf16.h>

#define IMG_H 256
#define IMG_W 256
#define NB 4
#define NK 4

#define TILE_W 32
#define TILE_H 16
#define SM_W   36          // TILE_W + 2 left + 2 right halo
#define SM_H   18          // TILE_H + 2 bottom halo (no top halo needed)
#define GRID_BLOCKS ((IMG_W / TILE_W) * (IMG_H / TILE_H) * NB)   // 8*16*4 = 512

// Accumulators: [b][0..3] = numerator_k, [b][4..7] = denominator_k
// Zero at module load; last block resets after each run (graph-replay safe).
__device__ float        g_acc[NB][8];
__device__ unsigned int g_ticket;

// exp(-u/100) for u in [0,1]; trunc err <= ~4e-10
__device__ __forceinline__ float expw(float u) {
    return fmaf(u, fmaf(u, fmaf(u, -1.6666667e-7f, 5.0e-5f), -0.01f), 1.0f);
}

// Pair-symmetric formulation. Positive-direction offsets (dy>0)||(dy==0&&dx>0)
// of the 21-tap mask dsq<=5; 10 offsets + center.
__global__ __launch_bounds__(256, 4)
void sncl_fused_kernel(const float* __restrict__ image,
                       const float* __restrict__ enc,
                       float* __restrict__ out) {
    const int b   = blockIdx.z;
    const int tx0 = blockIdx.x * TILE_W;
    const int ty0 = blockIdx.y * TILE_H;

    __shared__ float  sgray[SM_H][SM_W];
    __shared__ float4 senc [SM_H][SM_W];
    __shared__ float  part [8][8];

    const int tid = threadIdx.y * 32 + threadIdx.x;
    const float* img0 = image + (size_t)b * 3 * IMG_H * IMG_W;
    const float* e0   = enc   + (size_t)b * 4 * IMG_H * IMG_W;
    const int HW = IMG_H * IMG_W;

    // Halo load: rows gy = ty0 .. ty0+17, cols gx = tx0-2 .. tx0+33. OOB => 0.
    for (int i = tid; i < SM_H * SM_W; i += 256) {
        int ly = i / SM_W, lx = i - ly * SM_W;
        int gy = ty0 + ly, gx = tx0 - 2 + lx;
        float g = 0.0f;
        float4 e = make_float4(0.f, 0.f, 0.f, 0.f);
        if ((unsigned)gy < IMG_H && (unsigned)gx < IMG_W) {
            int off = gy * IMG_W + gx;
            g = (img0[off] + img0[HW + off] + img0[2 * HW + off]) * (1.0f / 3.0f);
            e.x = e0[off];
            e.y = e0[HW + off];
            e.z = e0[2 * HW + off];
            e.w = e0[3 * HW + off];
        }
        sgray[ly][lx] = g;
        senc [ly][lx] = e;
    }
    __syncthreads();

    const int PDY[10] = { 0, 0, 1, 1, 1, 1, 1, 2, 2, 2 };
    const int PDX[10] = { 1, 2, -2, -1, 0, 1, 2, -1, 0, 1 };
    const float PDW[10] = {
        0.93941306f, 0.77880078f,
        0.73161563f, 0.88249690f, 0.93941306f, 0.88249690f, 0.73161563f,
        0.73161563f, 0.77880078f, 0.73161563f
    };

    float acc[8];
    #pragma unroll
    for (int j = 0; j < 8; j++) acc[j] = 0.0f;

    // Two pixels per thread: rows threadIdx.y and threadIdx.y + 8
    #pragma unroll
    for (int half = 0; half < 2; half++) {
        const int ly = threadIdx.y + half * 8;
        const int lx = threadIdx.x + 2;
        const int gy = ty0 + ly;
        const int gx = tx0 + threadIdx.x;

        const float  c  = sgray[ly][lx];
        const float4 ec = senc [ly][lx];

        float wsum = 0.0f;
        float4 nom = make_float4(0.f, 0.f, 0.f, 0.f);
        #pragma unroll
        for (int p = 0; p < 10; p++) {
            float g = sgray[ly + PDY[p]][lx + PDX[p]];
            float d = g - c;
            float w = PDW[p] * expw(d * d);
            wsum += w;
            float4 e = senc[ly + PDY[p]][lx + PDX[p]];
            nom.x = fmaf(w, e.x, nom.x);
            nom.y = fmaf(w, e.y, nom.y);
            nom.z = fmaf(w, e.z, nom.z);
            nom.w = fmaf(w, e.w, nom.w);
        }

        // Negative-direction OOB taps (neighbor i-delta off the image):
        // only top (gy<2), left (gx<2), right (gx>253) pixels. g_j=0 => same
        // exp factor exp(-c^2/100) for all; sum the spatial weights.
        float S = 0.0f;
        if (gy < 2 || gx < 2 || gx > IMG_W - 3) {
            #pragma unroll
            for (int p = 0; p < 10; p++) {
                int ny = gy - PDY[p];
                int nx = gx - PDX[p];
                if (ny < 0 || (unsigned)nx >= (unsigned)IMG_W) S += PDW[p];
            }
        }
        // wsum_i total = 2-direction pair weights + center(1) + OOB-neg
        float wself = wsum;                 // pair side handled via den formula
        float wcorr = 1.0f + S * expw(c * c);

        // num contrib: ec o (2*nom) [pairs, both sides] + ec o ec [center]
        acc[0] = fmaf(ec.x, fmaf(2.0f, nom.x, ec.x), acc[0]);
        acc[1] = fmaf(ec.y, fmaf(2.0f, nom.y, ec.y), acc[1]);
        acc[2] = fmaf(ec.z, fmaf(2.0f, nom.z, ec.z), acc[2]);
        acc[3] = fmaf(ec.w, fmaf(2.0f, nom.w, ec.w), acc[3]);
        // den contrib: ec*(wsum_pairs + 1 + oob) + nom (the e_j side of pairs)
        float wd = wself + wcorr;
        acc[4] += fmaf(ec.x, wd, nom.x);
        acc[5] += fmaf(ec.y, wd, nom.y);
        acc[6] += fmaf(ec.z, wd, nom.z);
        acc[7] += fmaf(ec.w, wd, nom.w);
    }

    // Warp reduce (blockDim.x == 32, warp == threadIdx.y)
    #pragma unroll
    for (int o = 16; o > 0; o >>= 1) {
        #pragma unroll
        for (int j = 0; j < 8; j++)
            acc[j] += __shfl_down_sync(0xffffffffu, acc[j], o);
    }
    if (threadIdx.x == 0) {
        #pragma unroll
        for (int j = 0; j < 8; j++)
            part[threadIdx.y][j] = acc[j];
    }
    __syncthreads();

    if (tid < 8) {
        float s = 0.0f;
        #pragma unroll
        for (int w = 0; w < 8; w++) s += part[w][tid];
        atomicAdd(&g_acc[b][tid], s);
    }
    __syncthreads();

    // Last-block finalize
    __shared__ bool is_last;
    if (tid == 0) {
        __threadfence();
        unsigned int old = atomicAdd(&g_ticket, 1u);
        is_last = (old == (unsigned int)(GRID_BLOCKS - 1));
    }
    __syncthreads();

    if (is_last && tid == 0) {
        __threadfence();
        float total = 0.0f;
        #pragma unroll
        for (int bb = 0; bb < NB; bb++) {
            float s = 0.0f;
            #pragma unroll
            for (int k = 0; k < NK; k++)
                s += g_acc[bb][k] / (g_acc[bb][4 + k] + 1e-8f);
            total += (float)NK - s;
        }
        out[0] = total * (1.0f / NB);
        #pragma unroll
        for (int j = 0; j < NB * 8; j++) ((float*)g_acc)[j] = 0.0f;
        __threadfence();
        g_ticket = 0u;
    }
}

extern "C" void kernel_launch(void* const* d_in, const int* in_sizes, int n_in,
                              void* d_out, int out_size) {
    const float* image = (const float*)d_in[0];
    const float* enc   = (const float*)d_in[1];
    float* out = (float*)d_out;

    dim3 blk(32, 8, 1);
    dim3 grd(IMG_W / TILE_W, IMG_H / TILE_H, NB);
    sncl_fused_kernel<<<grd, blk>>>(image, enc, out);
}

// round 4
// speedup vs baseline: 1.1775x; 1.0175x over previous
#include <cuda_runtime.h>
#include <cuda_bf16.h>

#define IMG_H 256
#define IMG_W 256
#define NB 4
#define NK 4

#define TILE_W 32
#define TILE_H 8
#define SM_W   36          // TILE_W + 2 left + 2 right halo
#define SM_H   10          // TILE_H + 2 bottom halo (no top halo needed)
#define GRID_BLOCKS ((IMG_W / TILE_W) * (IMG_H / TILE_H) * NB)   // 8*32*4 = 1024

// Accumulators: [b][0..3] = numerator_k, [b][4..7] = denominator_k
// Zero at module load; last block resets after each run (graph-replay safe).
__device__ float        g_acc[NB][8];
__device__ unsigned int g_ticket;

// Pair-symmetric formulation: positive-direction offsets (dy>0)||(dy==0&&dx>0)
// of the 21-tap mask dsq<=5. 10 offsets + center.
__global__ __launch_bounds__(256, 7)
void sncl_fused_kernel(const float* __restrict__ image,
                       const float* __restrict__ enc,
                       float* __restrict__ out) {
    const int b   = blockIdx.z;
    const int tx0 = blockIdx.x * TILE_W;
    const int ty0 = blockIdx.y * TILE_H;

    __shared__ float  sgray[SM_H][SM_W];
    __shared__ float4 senc [SM_H][SM_W];
    __shared__ float  part [8][8];

    const int tid = threadIdx.y * 32 + threadIdx.x;
    const float* img0 = image + (size_t)b * 3 * IMG_H * IMG_W;
    const float* e0   = enc   + (size_t)b * 4 * IMG_H * IMG_W;
    const int HW = IMG_H * IMG_W;

    // Halo load: rows gy = ty0 .. ty0+9, cols gx = tx0-2 .. tx0+33. OOB => 0.
    #pragma unroll
    for (int i = tid; i < SM_H * SM_W; i += 256) {
        int ly = i / SM_W, lx = i - ly * SM_W;
        int gy = ty0 + ly, gx = tx0 - 2 + lx;
        float g = 0.0f;
        float4 e = make_float4(0.f, 0.f, 0.f, 0.f);
        if ((unsigned)gy < IMG_H && (unsigned)gx < IMG_W) {
            int off = gy * IMG_W + gx;
            g = (img0[off] + img0[HW + off] + img0[2 * HW + off]) * (1.0f / 3.0f);
            e.x = e0[off];
            e.y = e0[HW + off];
            e.z = e0[2 * HW + off];
            e.w = e0[3 * HW + off];
        }
        sgray[ly][lx] = g;
        senc [ly][lx] = e;
    }
    __syncthreads();

    const int PDY[10] = { 0, 0, 1, 1, 1, 1, 1, 2, 2, 2 };
    const int PDX[10] = { 1, 2, -2, -1, 0, 1, 2, -1, 0, 1 };
    const float PDW[10] = {
        0.93941306f, 0.77880078f,
        0.73161563f, 0.88249690f, 0.93941306f, 0.88249690f, 0.73161563f,
        0.73161563f, 0.77880078f, 0.73161563f
    };

    const int ly = threadIdx.y;
    const int lx = threadIdx.x + 2;
    const int gy = ty0 + ly;
    const int gx = tx0 + threadIdx.x;

    const float  c  = sgray[ly][lx];
    const float4 ec = senc [ly][lx];

    float wsum = 0.0f;
    float4 nom = make_float4(0.f, 0.f, 0.f, 0.f);
    #pragma unroll
    for (int p = 0; p < 10; p++) {
        float g  = sgray[ly + PDY[p]][lx + PDX[p]];
        float d  = g - c;
        float d2 = d * d;
        // w = DW * exp(-d2/100) ~= DW*(1 - 0.01 d2 + 5e-5 d2^2); |err| <= 1.7e-7
        float w = fmaf(d2, fmaf(d2, PDW[p] * 5.0e-5f, PDW[p] * -0.01f), PDW[p]);
        wsum += w;
        float4 e = senc[ly + PDY[p]][lx + PDX[p]];
        nom.x = fmaf(w, e.x, nom.x);
        nom.y = fmaf(w, e.y, nom.y);
        nom.z = fmaf(w, e.z, nom.z);
        nom.w = fmaf(w, e.w, nom.w);
    }

    // Negative-direction OOB taps: only pixels with gy<2 || gx<2 || gx>253.
    // Neighbor gray is 0 => common factor exp(-c^2/100); sum spatial weights.
    float S = 0.0f;
    if (gy < 2 || gx < 2 || gx > IMG_W - 3) {
        #pragma unroll
        for (int p = 0; p < 10; p++) {
            int ny = gy - PDY[p];
            int nx = gx - PDX[p];
            if (ny < 0 || (unsigned)nx >= (unsigned)IMG_W) S += PDW[p];
        }
    }
    float c2 = c * c;
    float wd = wsum + fmaf(S, fmaf(c2, fmaf(c2, 5.0e-5f, -0.01f), 1.0f), 1.0f);

    float vals[8];
    // num: ec o (2*nom) [both sides of each pair] + ec o ec [center tap]
    vals[0] = ec.x * fmaf(2.0f, nom.x, ec.x);
    vals[1] = ec.y * fmaf(2.0f, nom.y, ec.y);
    vals[2] = ec.z * fmaf(2.0f, nom.z, ec.z);
    vals[3] = ec.w * fmaf(2.0f, nom.w, ec.w);
    // den: ec*(pair weights + center + OOB) + nom (e_j side of pairs)
    vals[4] = fmaf(ec.x, wd, nom.x);
    vals[5] = fmaf(ec.y, wd, nom.y);
    vals[6] = fmaf(ec.z, wd, nom.z);
    vals[7] = fmaf(ec.w, wd, nom.w);

    // Warp reduce (blockDim.x == 32, warp == threadIdx.y)
    #pragma unroll
    for (int o = 16; o > 0; o >>= 1) {
        #pragma unroll
        for (int j = 0; j < 8; j++)
            vals[j] += __shfl_down_sync(0xffffffffu, vals[j], o);
    }
    if (threadIdx.x == 0) {
        #pragma unroll
        for (int j = 0; j < 8; j++)
            part[threadIdx.y][j] = vals[j];
    }
    __syncthreads();

    if (tid < 8) {
        float s = 0.0f;
        #pragma unroll
        for (int w = 0; w < 8; w++) s += part[w][tid];
        atomicAdd(&g_acc[b][tid], s);
    }
    __syncthreads();

    // Last-block finalize
    __shared__ bool is_last;
    if (tid == 0) {
        __threadfence();
        unsigned int old = atomicAdd(&g_ticket, 1u);
        is_last = (old == (unsigned int)(GRID_BLOCKS - 1));
    }
    __syncthreads();

    if (is_last && tid == 0) {
        __threadfence();
        float total = 0.0f;
        #pragma unroll
        for (int bb = 0; bb < NB; bb++) {
            float s = 0.0f;
            #pragma unroll
            for (int k = 0; k < NK; k++)
                s += g_acc[bb][k] / (g_acc[bb][4 + k] + 1e-8f);
            total += (float)NK - s;
        }
        out[0] = total * (1.0f / NB);
        #pragma unroll
        for (int j = 0; j < NB * 8; j++) ((float*)g_acc)[j] = 0.0f;
        __threadfence();
        g_ticket = 0u;
    }
}

extern "C" void kernel_launch(void* const* d_in, const int* in_sizes, int n_in,
                              void* d_out, int out_size) {
    const float* image = (const float*)d_in[0];
    const float* enc   = (const float*)d_in[1];
    float* out = (float*)d_out;

    dim3 blk(32, 8, 1);
    dim3 grd(IMG_W / TILE_W, IMG_H / TILE_H, NB);
    sncl_fused_kernel<<<grd, blk>>>(image, enc, out);
}